// round 15
// baseline (speedup 1.0000x reference)
#include <cuda_runtime.h>
#include <cuda_bf16.h>

// SoftEmbeddedDecisionRules: balanced binary hierarchy over C=1024 classes.
// Two warps per row (512 classes each), 256-bit global accesses:
// lane L owns 8 contiguous classes [8L, 8L+8) of each of the warp's two
// 256-class spans -> one LDG.E.256 + one STG.E.256 per lane per span.
// seg 1/2/4 lane-local; seg 8..128 shfl butterfly on 8-sums; seg 256
// warp-local; seg 512 via 2-float smem exchange between the row's warp pair.
// sigmoid(x/seg) = 0.5*tanh(x/(2seg)) + 0.5 — one MUFU per sigmoid.

#define BATCH_N 32768
#define NCLASS 1024

__device__ __forceinline__ float sigmoid_scaled(float d, float inv2seg) {
    float t;
    asm("tanh.approx.f32 %0, %1;" : "=f"(t) : "f"(d * inv2seg));
    return fmaf(0.5f, t, 0.5f);
}

__device__ __forceinline__ void ldg256(const float* p, float* v) {
    asm("ld.global.nc.v8.f32 {%0,%1,%2,%3,%4,%5,%6,%7}, [%8];"
        : "=f"(v[0]), "=f"(v[1]), "=f"(v[2]), "=f"(v[3]),
          "=f"(v[4]), "=f"(v[5]), "=f"(v[6]), "=f"(v[7])
        : "l"(p));
}

__device__ __forceinline__ void stg256(float* p, const float* v) {
    asm volatile("st.global.v8.f32 [%0], {%1,%2,%3,%4,%5,%6,%7,%8};"
        :: "l"(p),
           "f"(v[0]), "f"(v[1]), "f"(v[2]), "f"(v[3]),
           "f"(v[4]), "f"(v[5]), "f"(v[6]), "f"(v[7])
        : "memory");
}

__global__ void __launch_bounds__(256, 5)
soft_tree_kernel(const float* __restrict__ in, float* __restrict__ out) {
    __shared__ float sx[4][2];   // per-row warp-pair exchange (4 rows/block)

    const int tid   = threadIdx.x;
    const int wib   = tid >> 5;                 // warp in block (0..7)
    const int lane  = tid & 31;
    const int rowib = wib >> 1;                 // row in block (0..3)
    const int half  = wib & 1;                  // which 512-class half
    const int row   = blockIdx.x * 4 + rowib;

    const float* gin  = in  + (size_t)row * NCLASS + half * 512;
    float*       gout = out + (size_t)row * NCLASS + half * 512;

    float fl[8];    // leaf factors: 4 per span
    float a2[4];    // seg=2 factors: 2 per span
    float a4[2];    // seg=4 factor: 1 per span
    float Bf[2];    // butterfly product seg 8..128, per span
    float G[2];     // 256-span sums (lane-uniform)

#pragma unroll
    for (int g = 0; g < 2; g++) {
        float v[8];
        ldg256(gin + g * 256 + lane * 8, v);    // coalesced 256-bit

        // seg=1 leaves
        fl[4 * g + 0] = sigmoid_scaled(v[0] - v[1], 0.5f);
        fl[4 * g + 1] = sigmoid_scaled(v[2] - v[3], 0.5f);
        fl[4 * g + 2] = sigmoid_scaled(v[4] - v[5], 0.5f);
        fl[4 * g + 3] = sigmoid_scaled(v[6] - v[7], 0.5f);

        // seg=2
        float t0 = v[0] + v[1], t1 = v[2] + v[3];
        float t2 = v[4] + v[5], t3 = v[6] + v[7];
        a2[2 * g + 0] = sigmoid_scaled(t0 - t1, 0.25f);
        a2[2 * g + 1] = sigmoid_scaled(t2 - t3, 0.25f);

        // seg=4
        float u0 = t0 + t1, u1 = t2 + t3;
        a4[g] = sigmoid_scaled(u0 - u1, 0.125f);

        // butterfly: seg = 8, 16, 32, 64, 128 on the lane's 8-sum
        float u = u0 + u1;
        float B, o;
        o = __shfl_xor_sync(0xffffffffu, u, 1);
        B  = sigmoid_scaled(u - o, 1.0f / 16.0f);   u += o;
        o = __shfl_xor_sync(0xffffffffu, u, 2);
        B *= sigmoid_scaled(u - o, 1.0f / 32.0f);   u += o;
        o = __shfl_xor_sync(0xffffffffu, u, 4);
        B *= sigmoid_scaled(u - o, 1.0f / 64.0f);   u += o;
        o = __shfl_xor_sync(0xffffffffu, u, 8);
        B *= sigmoid_scaled(u - o, 1.0f / 128.0f);  u += o;
        o = __shfl_xor_sync(0xffffffffu, u, 16);
        B *= sigmoid_scaled(u - o, 1.0f / 256.0f);  u += o;
        Bf[g] = B;
        G[g]  = u;                              // 256-sum, lane-uniform
    }

    // ---- seg=256 (warp-local) and seg=512 (pair exchange) ----
    float c = sigmoid_scaled(G[0] - G[1], 1.0f / 512.0f);
    float S = G[0] + G[1];                      // this warp's 512-sum

    if (lane == 0) sx[rowib][half] = S;
    __syncthreads();
    float So  = sx[rowib][half ^ 1];
    float top = sigmoid_scaled(S - So, 1.0f / 1024.0f);  // factors sum to 1

    float i0 = top * c, i1 = top - i0;          // span path products
    float T[2] = { i0, i1 };

    // ---- downsweep + 256-bit coalesced store ----
#pragma unroll
    for (int g = 0; g < 2; g++) {
        float P8  = T[g] * Bf[g];               // lane's 8-class block prob
        float p4a = P8 * a4[g];
        float p4b = P8 - p4a;
        float q0 = p4a * a2[2 * g];     float q1 = p4a - q0;
        float q2 = p4b * a2[2 * g + 1]; float q3 = p4b - q2;

        float w[8];
        w[0] = q0 * fl[4 * g + 0];  w[1] = q0 - w[0];
        w[2] = q1 * fl[4 * g + 1];  w[3] = q1 - w[2];
        w[4] = q2 * fl[4 * g + 2];  w[5] = q2 - w[4];
        w[6] = q3 * fl[4 * g + 3];  w[7] = q3 - w[6];

        stg256(gout + g * 256 + lane * 8, w);   // coalesced 256-bit
    }
}

extern "C" void kernel_launch(void* const* d_in, const int* in_sizes, int n_in,
                              void* d_out, int out_size) {
    (void)in_sizes; (void)n_in; (void)out_size;
    const float* in = (const float*)d_in[0];
    float* out = (float*)d_out;
    // 32768 rows, 2 warps per row, 4 rows/block -> 8192 blocks
    soft_tree_kernel<<<BATCH_N / 4, 256>>>(in, out);
}